// round 15
// baseline (speedup 1.0000x reference)
#include <cuda_runtime.h>
#include <cuda_bf16.h>

#define NSEQ   512
#define NBATCH 64
#define NHID   1024
#define NCAP   16
#define NDIM   64
#define NSPLIT 4
#define SCHUNK 128   // NSEQ / NSPLIT
#define NPART  16

typedef unsigned uu;

// Scratch (device globals — no allocation allowed)
__device__ __align__(256) float g_V[NBATCH * NCAP * NHID];                  // 4 MB
// Y layout: [b][nc][h][split]
__device__ __align__(256) float g_Y[NBATCH * NCAP * NHID * NSPLIT];         // 16 MB
__device__ __align__(256) float g_opart[NPART * NBATCH * NCAP * NDIM];      // 4 MB
__device__ __align__(256) __nv_bfloat16 g_Xh[(size_t)NSEQ * NBATCH * NHID]; // 64 MB
__device__ __align__(256) __nv_bfloat16 g_Xl[(size_t)NSEQ * NBATCH * NHID]; // 64 MB
__device__ __align__(256) __nv_bfloat16 g_Vh[NBATCH * NCAP * NHID];         // 2 MB
__device__ __align__(256) __nv_bfloat16 g_Vl[NBATCH * NCAP * NHID];         // 2 MB

__device__ __forceinline__ void fma4(float4 &a, float4 x, float c) {
    a.x = fmaf(c, x.x, a.x);
    a.y = fmaf(c, x.y, a.y);
    a.z = fmaf(c, x.z, a.z);
    a.w = fmaf(c, x.w, a.w);
}

__device__ __forceinline__ void cvt_hilo(float4 x, uint2 &uh, uint2 &ul) {
    __nv_bfloat16 h0 = __float2bfloat16_rn(x.x);
    __nv_bfloat16 h1 = __float2bfloat16_rn(x.y);
    __nv_bfloat16 h2 = __float2bfloat16_rn(x.z);
    __nv_bfloat16 h3 = __float2bfloat16_rn(x.w);
    __nv_bfloat16 l0 = __float2bfloat16_rn(x.x - __bfloat162float(h0));
    __nv_bfloat16 l1 = __float2bfloat16_rn(x.y - __bfloat162float(h1));
    __nv_bfloat16 l2 = __float2bfloat16_rn(x.z - __bfloat162float(h2));
    __nv_bfloat16 l3 = __float2bfloat16_rn(x.w - __bfloat162float(h3));
    __nv_bfloat162 ph01 = __halves2bfloat162(h0, h1);
    __nv_bfloat162 ph23 = __halves2bfloat162(h2, h3);
    __nv_bfloat162 pl01 = __halves2bfloat162(l0, l1);
    __nv_bfloat162 pl23 = __halves2bfloat162(l2, l3);
    uh.x = reinterpret_cast<uu&>(ph01); uh.y = reinterpret_cast<uu&>(ph23);
    ul.x = reinterpret_cast<uu&>(pl01); ul.y = reinterpret_cast<uu&>(pl23);
}

// ---- mma.sync / ldmatrix / cp.async helpers ----
__device__ __forceinline__ uu su(const void* p) { return (uu)__cvta_generic_to_shared(p); }
__device__ __forceinline__ void ldm4(uu a, uu &r0, uu &r1, uu &r2, uu &r3) {
    asm volatile("ldmatrix.sync.aligned.m8n8.x4.shared.b16 {%0,%1,%2,%3},[%4];"
                 : "=r"(r0), "=r"(r1), "=r"(r2), "=r"(r3) : "r"(a));
}
__device__ __forceinline__ void ldm4t(uu a, uu &r0, uu &r1, uu &r2, uu &r3) {
    asm volatile("ldmatrix.sync.aligned.m8n8.x4.trans.shared.b16 {%0,%1,%2,%3},[%4];"
                 : "=r"(r0), "=r"(r1), "=r"(r2), "=r"(r3) : "r"(a));
}
__device__ __forceinline__ void ldm2(uu a, uu &r0, uu &r1) {
    asm volatile("ldmatrix.sync.aligned.m8n8.x2.shared.b16 {%0,%1},[%2];"
                 : "=r"(r0), "=r"(r1) : "r"(a));
}
__device__ __forceinline__ void mma16816(float* c, uu a0, uu a1, uu a2, uu a3, uu b0, uu b1) {
    asm volatile(
        "mma.sync.aligned.m16n8k16.row.col.f32.bf16.bf16.f32 "
        "{%0,%1,%2,%3},{%4,%5,%6,%7},{%8,%9},{%0,%1,%2,%3};"
        : "+f"(c[0]), "+f"(c[1]), "+f"(c[2]), "+f"(c[3])
        : "r"(a0), "r"(a1), "r"(a2), "r"(a3), "r"(b0), "r"(b1));
}
__device__ __forceinline__ void cpa16(uu dst, const void* src) {
    asm volatile("cp.async.cg.shared.global [%0], [%1], 16;" :: "r"(dst), "l"(src));
}
#define CPA_COMMIT() asm volatile("cp.async.commit_group;" ::: "memory")
#define CPA_WAIT1()  asm volatile("cp.async.wait_group 1;" ::: "memory")
#define CPA_WAIT0()  asm volatile("cp.async.wait_group 0;" ::: "memory")

// SMEM layout (byte offsets). 64-k chunks; padded rows.
#define XROW   144
#define XBUF   36864
#define XLOFF  18432
#define SM_V   73728
#define VBUF   4608
#define VLOFF  2304
#define SM_L   82944
#define SM_CH  91136
#define SM_CL  95488
#define SM_TOTAL 99840
#define CROW   272

// ---------------------------------------------------------------------------
// pass_kernel — identical math to R14; PDL: trigger at entry (iter>=1),
// X chunk-0 prefetch before gridsync (Xh stable), V loads after gridsync.
// Stage B walks chunks in reverse (L2 reuse).
// ---------------------------------------------------------------------------
__global__ void __launch_bounds__(256, 2)
pass_kernel(const float* __restrict__ X, int iter) {
    extern __shared__ char smraw[];
    float*         lsh  = reinterpret_cast<float*>(smraw + SM_L);
    __nv_bfloat16* smCh = reinterpret_cast<__nv_bfloat16*>(smraw + SM_CH);
    __nv_bfloat16* smCl = reinterpret_cast<__nv_bfloat16*>(smraw + SM_CL);

    const int b     = blockIdx.y;
    const int split = blockIdx.x;
    const int t     = threadIdx.x;
    const int lane  = t & 31;
    const int w     = t >> 5;
    const int s0    = split * SCHUNK;

    if (iter == 0) {
        // Writes Xh/Xl/Y: must wait for full predecessor completion first.
        // No early trigger (implicit at kernel end) — successors of this
        // kernel must see Xh fully written before their prologue reads it.
        cudaGridDependencySynchronize();
        const float4* X4 = reinterpret_cast<const float4*>(X);
        const size_t xstride = (size_t)NBATCH * (NHID / 4);
        const size_t base = ((size_t)s0 * NBATCH + b) * (NHID / 4) + t;
        uint2* Xh2 = reinterpret_cast<uint2*>(g_Xh);
        uint2* Xl2 = reinterpret_cast<uint2*>(g_Xl);
        float4 a = make_float4(0.f, 0.f, 0.f, 0.f);
        #pragma unroll 8
        for (int s = 0; s < SCHUNK; ++s) {
            const size_t idx = base + (size_t)s * xstride;
            float4 x = X4[idx];
            a.x += x.x; a.y += x.y; a.z += x.z; a.w += x.w;
            uint2 uh, ul;
            cvt_hilo(x, uh, ul);
            Xh2[idx] = uh;
            Xl2[idx] = ul;
        }
        const float c = 1.0f / 16.0f;
        a.x *= c; a.y *= c; a.z *= c; a.w *= c;
        float* Y0 = g_Y + ((size_t)b * NCAP * NHID) * NSPLIT + split;
        Y0[(size_t)(4 * t + 0) * 4] = a.x;
        Y0[(size_t)(4 * t + 1) * 4] = a.y;
        Y0[(size_t)(4 * t + 2) * 4] = a.z;
        Y0[(size_t)(4 * t + 3) * 4] = a.w;
        return;
    }

    // Let the next kernel (u1) launch and run its W prologue concurrently.
    cudaTriggerProgrammaticLaunchCompletion();

    const uu smb = su(smraw);

    auto loadX = [&](int kc, int buf) {
        const uu dst = smb + (uu)(buf * XBUF);
        #pragma unroll
        for (int r = 0; r < 4; ++r) {
            int idx = t + r * 256;
            int row = idx >> 3, c8 = idx & 7;
            size_t gb = ((size_t)(s0 + row) * NBATCH + b) * NHID + kc * 64 + c8 * 8;
            cpa16(dst + row * XROW + c8 * 16,         g_Xh + gb);
            cpa16(dst + XLOFF + row * XROW + c8 * 16, g_Xl + gb);
        }
    };
    auto loadV = [&](int kc, int buf) {
        const uu dst = smb + SM_V + (uu)(buf * VBUF);
        if (t < 128) {
            int row = t >> 3, c8 = t & 7;
            size_t vb = ((size_t)b * NCAP + row) * NHID + kc * 64 + c8 * 8;
            cpa16(dst + row * XROW + c8 * 16,         g_Vh + vb);
            cpa16(dst + VLOFF + row * XROW + c8 * 16, g_Vl + vb);
        }
    };

    // ---- PDL prologue: X chunk 0 is independent of the predecessor ----
    loadX(0, 0); CPA_COMMIT();
    cudaGridDependencySynchronize();   // V (and Y-write targets) now safe
    loadV(0, 0);
    loadX(1, 1); loadV(1, 1); CPA_COMMIT();

    // ============================ Stage A ============================
    float acc[2][4];
    #pragma unroll
    for (int i = 0; i < 2; ++i)
        #pragma unroll
        for (int k = 0; k < 4; ++k) acc[i][k] = 0.f;

    const uu aoffA = smb + (uu)((w * 16 + (lane & 7) + ((lane >> 3) & 1) * 8) * XROW + (lane >> 4) * 16);
    const uu boffA = smb + SM_V + (uu)((lane & 7) * XROW + ((lane >> 3) & 1) * 16);

    for (int kc = 0; kc < 16; ++kc) {
        if (kc >= 1 && kc < 15) {
            loadX(kc + 1, (kc + 1) & 1);
            loadV(kc + 1, (kc + 1) & 1);
            CPA_COMMIT();
            CPA_WAIT1();
        } else {
            CPA_WAIT0();   // kc==0 (drain X0+V0+X1+V1) or kc==15
        }
        __syncthreads();
        const uu xb0 = (uu)((kc & 1) * XBUF);
        const uu vb0 = (uu)((kc & 1) * VBUF);
        #pragma unroll
        for (int ks = 0; ks < 4; ++ks) {
            uu a0, a1, a2, a3, l0, l1, l2, l3;
            ldm4(aoffA + xb0 + ks * 32,         a0, a1, a2, a3);
            ldm4(aoffA + xb0 + XLOFF + ks * 32, l0, l1, l2, l3);
            uu bh00, bh01, bh10, bh11, bl00, bl01, bl10, bl11;
            ldm2(boffA + vb0 + ks * 32,                        bh00, bh01);
            ldm2(boffA + vb0 + 8 * XROW + ks * 32,             bh10, bh11);
            ldm2(boffA + vb0 + VLOFF + ks * 32,                bl00, bl01);
            ldm2(boffA + vb0 + VLOFF + 8 * XROW + ks * 32,     bl10, bl11);
            mma16816(acc[0], a0, a1, a2, a3, bh00, bh01);
            mma16816(acc[0], a0, a1, a2, a3, bl00, bl01);
            mma16816(acc[0], l0, l1, l2, l3, bh00, bh01);
            mma16816(acc[1], a0, a1, a2, a3, bh10, bh11);
            mma16816(acc[1], a0, a1, a2, a3, bl10, bl11);
            mma16816(acc[1], l0, l1, l2, l3, bh10, bh11);
        }
        __syncthreads();
    }

    // Stage-B first prefetch (chunk 15 — reverse order) overlaps softmax.
    loadX(15, 0); CPA_COMMIT();

    // write logits to lsh[s][nc]
    {
        const int m  = lane >> 2;
        const int n2 = (lane & 3) * 2;
        const int sr = w * 16 + m;
        #pragma unroll
        for (int n8 = 0; n8 < 2; ++n8) {
            lsh[sr * 16 + n8 * 8 + n2]           = acc[n8][0];
            lsh[sr * 16 + n8 * 8 + n2 + 1]       = acc[n8][1];
            lsh[(sr + 8) * 16 + n8 * 8 + n2]     = acc[n8][2];
            lsh[(sr + 8) * 16 + n8 * 8 + n2 + 1] = acc[n8][3];
        }
    }
    __syncthreads();

    // softmax, write c^T[nc][s] as bf16 hi/lo
    if (t < SCHUNK) {
        float l[NCAP];
        #pragma unroll
        for (int i = 0; i < NCAP; ++i) l[i] = lsh[t * NCAP + i];
        float m = l[0];
        #pragma unroll
        for (int i = 1; i < NCAP; ++i) m = fmaxf(m, l[i]);
        float e[NCAP]; float ssum = 0.f;
        #pragma unroll
        for (int i = 0; i < NCAP; ++i) { e[i] = __expf(l[i] - m); ssum += e[i]; }
        float inv = 1.0f / ssum;
        #pragma unroll
        for (int i = 0; i < NCAP; ++i) {
            float c = e[i] * inv;
            __nv_bfloat16 ch = __float2bfloat16_rn(c);
            smCh[i * 136 + t] = ch;
            smCl[i * 136 + t] = __float2bfloat16_rn(c - __bfloat162float(ch));
        }
    }

    // ============================ Stage B (reverse chunk order) ============
    const int mt  = w & 3;
    const int nt8 = w >> 2;
    const uu aoffB = smb + (uu)(((lane & 7) + (lane >> 4) * 8) * XROW + (mt * 16 + ((lane >> 3) & 1) * 8) * 2);
    const uu coffH = su(smCh) + (uu)(nt8 * 8 * CROW + (lane & 7) * CROW + ((lane >> 3) & 1) * 16);
    const uu coffL = su(smCl) + (uu)(nt8 * 8 * CROW + (lane & 7) * CROW + ((lane >> 3) & 1) * 16);
    float* Yb = g_Y + ((size_t)b * NCAP * NHID) * NSPLIT + split;

    for (int i = 0; i < 16; ++i) {
        const int kc = 15 - i;
        if (i < 15) {
            loadX(kc - 1, (i + 1) & 1);
            CPA_COMMIT();
            CPA_WAIT1();
        } else {
            CPA_WAIT0();
        }
        __syncthreads();
        const uu xb0 = (uu)((i & 1) * XBUF);

        float y[4];
        y[0] = 0.f; y[1] = 0.f; y[2] = 0.f; y[3] = 0.f;

        #pragma unroll
        for (int ks = 0; ks < 8; ++ks) {
            uu a0, a1, a2, a3, l0, l1, l2, l3;
            ldm4t(aoffB + xb0 + ks * 16 * XROW,         a0, a1, a2, a3);
            ldm4t(aoffB + xb0 + XLOFF + ks * 16 * XROW, l0, l1, l2, l3);
            uu c0, c1, d0, d1;
            ldm2(coffH + ks * 32, c0, c1);
            ldm2(coffL + ks * 32, d0, d1);
            mma16816(y, a0, a1, a2, a3, c0, c1);
            mma16816(y, a0, a1, a2, a3, d0, d1);
            mma16816(y, l0, l1, l2, l3, c0, c1);
        }
        __syncthreads();

        const int m  = lane >> 2;
        const int n2 = (lane & 3) * 2;
        const int hg = kc * 64 + mt * 16 + m;
        const int nc = nt8 * 8 + n2;
        Yb[(size_t)(nc * NHID + hg) * 4]           = y[0];
        Yb[(size_t)((nc + 1) * NHID + hg) * 4]     = y[1];
        Yb[(size_t)(nc * NHID + hg + 8) * 4]       = y[2];
        Yb[(size_t)((nc + 1) * NHID + hg + 8) * 4] = y[3];
    }
}

// U1: W prologue before gridsync (PDL overlap); Y reads after.
__global__ void __launch_bounds__(256)
u1_kernel(const float* __restrict__ W, int iter) {
    __shared__ float Wsh[64 * 64];
    __shared__ float ysh[64 * 65];

    const int nc = blockIdx.x;
    const int p  = blockIdx.y;
    const int h0 = p * 64;
    const int t  = threadIdx.x;
    const int ncY = (iter == 0) ? 0 : nc;

    cudaTriggerProgrammaticLaunchCompletion();

    #pragma unroll
    for (int k = 0; k < 16; ++k) {
        int idx = t + k * 256;
        int hh = idx >> 6, dc = idx & 63;
        Wsh[hh * 64 + dc] = W[(size_t)(h0 + hh) * (NCAP * NDIM) + nc * NDIM + dc];
    }

    cudaGridDependencySynchronize();

    #pragma unroll
    for (int k = 0; k < 16; ++k) {
        int idx = t + k * 256;
        int b = idx >> 6, hh = idx & 63;
        float4 v = reinterpret_cast<const float4*>(g_Y)[
            (size_t)(b * NCAP + ncY) * NHID + h0 + hh];
        ysh[b * 65 + hh] = (v.x + v.y) + (v.z + v.w);
    }
    __syncthreads();

    const int dc4  = (t & 15) * 4;
    const int brow = (t >> 4) * 4;
    float4 a0 = make_float4(0,0,0,0), a1 = a0, a2 = a0, a3 = a0;
    #pragma unroll 4
    for (int hh = 0; hh < 64; ++hh) {
        float4 w4 = *reinterpret_cast<const float4*>(&Wsh[hh * 64 + dc4]);
        fma4(a0, w4, ysh[(brow + 0) * 65 + hh]);
        fma4(a1, w4, ysh[(brow + 1) * 65 + hh]);
        fma4(a2, w4, ysh[(brow + 2) * 65 + hh]);
        fma4(a3, w4, ysh[(brow + 3) * 65 + hh]);
    }
    #pragma unroll
    for (int i = 0; i < 4; ++i) {
        float4 a = (i == 0) ? a0 : (i == 1) ? a1 : (i == 2) ? a2 : a3;
        *reinterpret_cast<float4*>(g_opart + (((size_t)p * NBATCH + brow + i) * NCAP + nc) * NDIM + dc4) = a;
    }
}

// squash (iter 3 only)
__global__ void __launch_bounds__(256)
squash_kernel(float* __restrict__ Og) {
    cudaTriggerProgrammaticLaunchCompletion();
    cudaGridDependencySynchronize();

    const int b = blockIdx.x;
    const int t = threadIdx.x;
    const int nc = t >> 4;
    const int q  = t & 15;

    float4 a = make_float4(0,0,0,0);
    #pragma unroll
    for (int p = 0; p < NPART; ++p) {
        float4 v = *(reinterpret_cast<const float4*>(
            g_opart + (((size_t)p * NBATCH + b) * NCAP + nc) * NDIM) + q);
        a.x += v.x; a.y += v.y; a.z += v.z; a.w += v.w;
    }
    float ss = a.x * a.x + a.y * a.y + a.z * a.z + a.w * a.w;
    #pragma unroll
    for (int off = 8; off > 0; off >>= 1) ss += __shfl_xor_sync(0xffffffffu, ss, off);
    float inv = rsqrtf(ss + 1e-7f);
    a.x *= inv; a.y *= inv; a.z *= inv; a.w *= inv;

    *(reinterpret_cast<float4*>(Og + ((size_t)b * NCAP + nc) * NDIM) + q) = a;
}

// U2S (fused squash + u2, iters 0-2): W prologue before gridsync.
__global__ void __launch_bounds__(256)
u2s_kernel(const float* __restrict__ W, int iter) {
    __shared__ float WshT[64 * 68];
    __shared__ float osh[64 * 64];

    const int nc = blockIdx.x;
    const int p  = blockIdx.y;
    const int h0 = p * 64;
    const int t  = threadIdx.x;

    cudaTriggerProgrammaticLaunchCompletion();

    #pragma unroll
    for (int k = 0; k < 16; ++k) {
        int idx = t + k * 256;
        int hh = idx >> 6, dc = idx & 63;
        WshT[dc * 68 + hh] = W[(size_t)(h0 + hh) * (NCAP * NDIM) + nc * NDIM + dc];
    }

    cudaGridDependencySynchronize();

    // ---- Phase 0: load+sum opart, squash ----
    {
        const int b  = t >> 2;
        const int dq = (t & 3) * 4;
        float4 r0 = make_float4(0,0,0,0), r1 = r0, r2 = r0, r3 = r0;
        #pragma unroll
        for (int pp = 0; pp < NPART; ++pp) {
            const float4* src = reinterpret_cast<const float4*>(
                g_opart + (((size_t)pp * NBATCH + b) * NCAP + nc) * NDIM) + dq;
            float4 v0 = src[0], v1 = src[1], v2 = src[2], v3 = src[3];
            r0.x += v0.x; r0.y += v0.y; r0.z += v0.z; r0.w += v0.w;
            r1.x += v1.x; r1.y += v1.y; r1.z += v1.z; r1.w += v1.w;
            r2.x += v2.x; r2.y += v2.y; r2.z += v2.z; r2.w += v2.w;
            r3.x += v3.x; r3.y += v3.y; r3.z += v3.z; r3.w += v3.w;
        }
        float ss = r0.x*r0.x + r0.y*r0.y + r0.z*r0.z + r0.w*r0.w
                 + r1.x*r1.x + r1.y*r1.y + r1.z*r1.z + r1.w*r1.w
                 + r2.x*r2.x + r2.y*r2.y + r2.z*r2.z + r2.w*r2.w
                 + r3.x*r3.x + r3.y*r3.y + r3.z*r3.z + r3.w*r3.w;
        ss += __shfl_xor_sync(0xffffffffu, ss, 1);
        ss += __shfl_xor_sync(0xffffffffu, ss, 2);
        float inv = rsqrtf(ss + 1e-7f);
        float4* orow = reinterpret_cast<float4*>(&osh[b * 64]) + dq;
        r0.x *= inv; r0.y *= inv; r0.z *= inv; r0.w *= inv;
        r1.x *= inv; r1.y *= inv; r1.z *= inv; r1.w *= inv;
        r2.x *= inv; r2.y *= inv; r2.z *= inv; r2.w *= inv;
        r3.x *= inv; r3.y *= inv; r3.z *= inv; r3.w *= inv;
        orow[0] = r0; orow[1] = r1; orow[2] = r2; orow[3] = r3;
    }
    __syncthreads();

    // ---- Phase 1: rank update ----
    const int hh4  = (t & 15) * 4;
    const int brow = (t >> 4) * 4;
    float4 a0 = make_float4(0,0,0,0), a1 = a0, a2 = a0, a3 = a0;
    #pragma unroll 4
    for (int dc = 0; dc < 64; ++dc) {
        float4 w4 = *reinterpret_cast<const float4*>(&WshT[dc * 68 + hh4]);
        fma4(a0, w4, osh[(brow + 0) * 64 + dc]);
        fma4(a1, w4, osh[(brow + 1) * 64 + dc]);
        fma4(a2, w4, osh[(brow + 2) * 64 + dc]);
        fma4(a3, w4, osh[(brow + 3) * 64 + dc]);
    }
    #pragma unroll
    for (int i = 0; i < 4; ++i) {
        float4 a = (i == 0) ? a0 : (i == 1) ? a1 : (i == 2) ? a2 : a3;
        const size_t base = (((size_t)(brow + i)) * NCAP + nc) * NHID + h0 + hh4;
        float4* vp = reinterpret_cast<float4*>(g_V + base);
        float4 v;
        if (iter == 0) {
            v = a;
        } else {
            v = *vp;
            v.x += a.x; v.y += a.y; v.z += a.z; v.w += a.w;
        }
        *vp = v;
        uint2 uh, ul;
        cvt_hilo(v, uh, ul);
        *reinterpret_cast<uint2*>(g_Vh + base) = uh;
        *reinterpret_cast<uint2*>(g_Vl + base) = ul;
    }
}

// ---- host: launch with PDL attribute on the default (capture) stream ----
template <typename F, typename... Args>
static inline void launch_pdl(F f, dim3 grid, dim3 block, size_t smem, Args... args) {
    cudaLaunchConfig_t cfg = {};
    cfg.gridDim = grid;
    cfg.blockDim = block;
    cfg.dynamicSmemBytes = smem;
    cfg.stream = 0;
    cudaLaunchAttribute attr[1];
    attr[0].id = cudaLaunchAttributeProgrammaticStreamSerialization;
    attr[0].val.programmaticStreamSerializationAllowed = 1;
    cfg.attrs = attr;
    cfg.numAttrs = 1;
    cudaLaunchKernelEx(&cfg, f, args...);
}

extern "C" void kernel_launch(void* const* d_in, const int* in_sizes, int n_in,
                              void* d_out, int out_size) {
    (void)n_in; (void)out_size;
    const float* X = (const float*)d_in[0];
    const float* W = (const float*)d_in[1];
    if (in_sizes[0] == NHID * NCAP * NDIM) { const float* tmp = X; X = W; W = tmp; }

    cudaFuncSetAttribute(pass_kernel, cudaFuncAttributeMaxDynamicSharedMemorySize, SM_TOTAL);

    float* out = (float*)d_out;
    for (int iter = 0; iter < 4; ++iter) {
        launch_pdl(pass_kernel, dim3(NSPLIT, NBATCH), dim3(256), (size_t)SM_TOTAL, X, iter);
        launch_pdl(u1_kernel, dim3(NCAP, NPART), dim3(256), (size_t)0, W, iter);
        if (iter < 3) {
            launch_pdl(u2s_kernel, dim3(NCAP, NPART), dim3(256), (size_t)0, W, iter);
        } else {
            launch_pdl(squash_kernel, dim3(NBATCH), dim3(256), (size_t)0, out);
        }
    }
}

// round 16
// speedup vs baseline: 1.1105x; 1.1105x over previous
#include <cuda_runtime.h>
#include <cuda_bf16.h>

#define NSEQ   512
#define NBATCH 64
#define NHID   1024
#define NCAP   16
#define NDIM   64
#define NSPLIT 4
#define SCHUNK 128   // NSEQ / NSPLIT
#define NPART  16

typedef unsigned uu;

// Scratch (device globals — no allocation allowed)
__device__ __align__(256) float g_V[NBATCH * NCAP * NHID];                  // 4 MB
// Y layout: [b][nc][h][split]
__device__ __align__(256) float g_Y[NBATCH * NCAP * NHID * NSPLIT];         // 16 MB
__device__ __align__(256) float g_opart[NPART * NBATCH * NCAP * NDIM];      // 4 MB
__device__ __align__(256) __nv_bfloat16 g_Xh[(size_t)NSEQ * NBATCH * NHID]; // 64 MB
__device__ __align__(256) __nv_bfloat16 g_Xl[(size_t)NSEQ * NBATCH * NHID]; // 64 MB
__device__ __align__(256) __nv_bfloat16 g_Vh[NBATCH * NCAP * NHID];         // 2 MB
__device__ __align__(256) __nv_bfloat16 g_Vl[NBATCH * NCAP * NHID];         // 2 MB

__device__ __forceinline__ void fma4(float4 &a, float4 x, float c) {
    a.x = fmaf(c, x.x, a.x);
    a.y = fmaf(c, x.y, a.y);
    a.z = fmaf(c, x.z, a.z);
    a.w = fmaf(c, x.w, a.w);
}

__device__ __forceinline__ void cvt_hilo(float4 x, uint2 &uh, uint2 &ul) {
    __nv_bfloat16 h0 = __float2bfloat16_rn(x.x);
    __nv_bfloat16 h1 = __float2bfloat16_rn(x.y);
    __nv_bfloat16 h2 = __float2bfloat16_rn(x.z);
    __nv_bfloat16 h3 = __float2bfloat16_rn(x.w);
    __nv_bfloat16 l0 = __float2bfloat16_rn(x.x - __bfloat162float(h0));
    __nv_bfloat16 l1 = __float2bfloat16_rn(x.y - __bfloat162float(h1));
    __nv_bfloat16 l2 = __float2bfloat16_rn(x.z - __bfloat162float(h2));
    __nv_bfloat16 l3 = __float2bfloat16_rn(x.w - __bfloat162float(h3));
    __nv_bfloat162 ph01 = __halves2bfloat162(h0, h1);
    __nv_bfloat162 ph23 = __halves2bfloat162(h2, h3);
    __nv_bfloat162 pl01 = __halves2bfloat162(l0, l1);
    __nv_bfloat162 pl23 = __halves2bfloat162(l2, l3);
    uh.x = reinterpret_cast<uu&>(ph01); uh.y = reinterpret_cast<uu&>(ph23);
    ul.x = reinterpret_cast<uu&>(pl01); ul.y = reinterpret_cast<uu&>(pl23);
}

// ---- mma.sync / ldmatrix / cp.async helpers ----
__device__ __forceinline__ uu su(const void* p) { return (uu)__cvta_generic_to_shared(p); }
__device__ __forceinline__ void ldm4(uu a, uu &r0, uu &r1, uu &r2, uu &r3) {
    asm volatile("ldmatrix.sync.aligned.m8n8.x4.shared.b16 {%0,%1,%2,%3},[%4];"
                 : "=r"(r0), "=r"(r1), "=r"(r2), "=r"(r3) : "r"(a));
}
__device__ __forceinline__ void ldm4t(uu a, uu &r0, uu &r1, uu &r2, uu &r3) {
    asm volatile("ldmatrix.sync.aligned.m8n8.x4.trans.shared.b16 {%0,%1,%2,%3},[%4];"
                 : "=r"(r0), "=r"(r1), "=r"(r2), "=r"(r3) : "r"(a));
}
__device__ __forceinline__ void ldm2(uu a, uu &r0, uu &r1) {
    asm volatile("ldmatrix.sync.aligned.m8n8.x2.shared.b16 {%0,%1},[%2];"
                 : "=r"(r0), "=r"(r1) : "r"(a));
}
__device__ __forceinline__ void mma16816(float* c, uu a0, uu a1, uu a2, uu a3, uu b0, uu b1) {
    asm volatile(
        "mma.sync.aligned.m16n8k16.row.col.f32.bf16.bf16.f32 "
        "{%0,%1,%2,%3},{%4,%5,%6,%7},{%8,%9},{%0,%1,%2,%3};"
        : "+f"(c[0]), "+f"(c[1]), "+f"(c[2]), "+f"(c[3])
        : "r"(a0), "r"(a1), "r"(a2), "r"(a3), "r"(b0), "r"(b1));
}
__device__ __forceinline__ void cpa16(uu dst, const void* src) {
    asm volatile("cp.async.cg.shared.global [%0], [%1], 16;" :: "r"(dst), "l"(src));
}
#define CPA_COMMIT() asm volatile("cp.async.commit_group;" ::: "memory")
#define CPA_WAIT1()  asm volatile("cp.async.wait_group 1;" ::: "memory")
#define CPA_WAIT0()  asm volatile("cp.async.wait_group 0;" ::: "memory")

// SMEM layout (byte offsets). 64-k chunks; padded rows.
#define XROW   144        // 64 bf16 (128B) + 16B pad
#define XBUF   36864      // one X buffer: Xh (18432) + Xl (18432), 128 rows
#define XLOFF  18432
#define SM_V   73728      // 2 V buffers
#define VBUF   4608       // Vh (2304) + Vl (2304), 16 rows x 144B
#define VLOFF  2304
#define SM_L   82944      // 128 x 16 f32 = 8192
#define SM_CH  91136      // c^T hi: 16 x 136 bf16 = 4352
#define SM_CL  95488
#define SM_TOTAL 99840
#define CROW   272        // c^T row stride bytes (136 bf16)

// ---------------------------------------------------------------------------
// pass_kernel (tensor, cp.async double-buffered, 64-k chunks, 2 CTAs/SM):
// CTA = (split of 128 s, batch b), 256 thr / 8 warps.
// Stage A: L[128s x 16nc] = X · V^T   — chunks 0..15.
// Stage B: D[64h x 16nc] = X^T · C    — chunks 15..0 (REVERSE: stage-A tail
//          chunks are still L2-resident, converting DRAM misses to L2 hits).
// hi/lo split: hi·hi + hi·lo + lo·hi accumulated into the SAME fp32 acc.
// iter==0: exact mean path + fused fp32->bf16 hi/lo convert of X.
// ---------------------------------------------------------------------------
__global__ void __launch_bounds__(256, 2)
pass_kernel(const float* __restrict__ X, int iter) {
    extern __shared__ char smraw[];
    float*         lsh  = reinterpret_cast<float*>(smraw + SM_L);
    __nv_bfloat16* smCh = reinterpret_cast<__nv_bfloat16*>(smraw + SM_CH);
    __nv_bfloat16* smCl = reinterpret_cast<__nv_bfloat16*>(smraw + SM_CL);

    const int b     = blockIdx.y;
    const int split = blockIdx.x;
    const int t     = threadIdx.x;
    const int lane  = t & 31;
    const int w     = t >> 5;
    const int s0    = split * SCHUNK;

    if (iter == 0) {
        const float4* X4 = reinterpret_cast<const float4*>(X);
        const size_t xstride = (size_t)NBATCH * (NHID / 4);
        const size_t base = ((size_t)s0 * NBATCH + b) * (NHID / 4) + t;
        uint2* Xh2 = reinterpret_cast<uint2*>(g_Xh);
        uint2* Xl2 = reinterpret_cast<uint2*>(g_Xl);
        float4 a = make_float4(0.f, 0.f, 0.f, 0.f);
        #pragma unroll 8
        for (int s = 0; s < SCHUNK; ++s) {
            const size_t idx = base + (size_t)s * xstride;
            float4 x = X4[idx];
            a.x += x.x; a.y += x.y; a.z += x.z; a.w += x.w;
            uint2 uh, ul;
            cvt_hilo(x, uh, ul);
            Xh2[idx] = uh;
            Xl2[idx] = ul;
        }
        const float c = 1.0f / 16.0f;
        a.x *= c; a.y *= c; a.z *= c; a.w *= c;
        float* Y0 = g_Y + ((size_t)b * NCAP * NHID) * NSPLIT + split;
        Y0[(size_t)(4 * t + 0) * 4] = a.x;
        Y0[(size_t)(4 * t + 1) * 4] = a.y;
        Y0[(size_t)(4 * t + 2) * 4] = a.z;
        Y0[(size_t)(4 * t + 3) * 4] = a.w;
        return;
    }

    const uu smb = su(smraw);

    // async-load: one 128s x 64h chunk of X (hi+lo). 4 cp16/thread per half.
    auto loadX = [&](int kc, int buf) {
        const uu dst = smb + (uu)(buf * XBUF);
        #pragma unroll
        for (int r = 0; r < 4; ++r) {
            int idx = t + r * 256;
            int row = idx >> 3, c8 = idx & 7;
            size_t gb = ((size_t)(s0 + row) * NBATCH + b) * NHID + kc * 64 + c8 * 8;
            cpa16(dst + row * XROW + c8 * 16,         g_Xh + gb);
            cpa16(dst + XLOFF + row * XROW + c8 * 16, g_Xl + gb);
        }
    };
    // one 16nc x 64h chunk of V (hi+lo). threads < 128 only.
    auto loadV = [&](int kc, int buf) {
        const uu dst = smb + SM_V + (uu)(buf * VBUF);
        if (t < 128) {
            int row = t >> 3, c8 = t & 7;
            size_t vb = ((size_t)b * NCAP + row) * NHID + kc * 64 + c8 * 8;
            cpa16(dst + row * XROW + c8 * 16,         g_Vh + vb);
            cpa16(dst + VLOFF + row * XROW + c8 * 16, g_Vl + vb);
        }
    };

    // ============================ Stage A ============================
    float acc[2][4];
    #pragma unroll
    for (int i = 0; i < 2; ++i)
        #pragma unroll
        for (int k = 0; k < 4; ++k) acc[i][k] = 0.f;

    const uu aoffA = smb + (uu)((w * 16 + (lane & 7) + ((lane >> 3) & 1) * 8) * XROW + (lane >> 4) * 16);
    const uu boffA = smb + SM_V + (uu)((lane & 7) * XROW + ((lane >> 3) & 1) * 16);

    loadX(0, 0); loadV(0, 0); CPA_COMMIT();
    for (int kc = 0; kc < 16; ++kc) {
        if (kc < 15) {
            loadX(kc + 1, (kc + 1) & 1);
            loadV(kc + 1, (kc + 1) & 1);
            CPA_COMMIT();
            CPA_WAIT1();
        } else {
            CPA_WAIT0();
        }
        __syncthreads();
        const uu xb0 = (uu)((kc & 1) * XBUF);
        const uu vb0 = (uu)((kc & 1) * VBUF);
        #pragma unroll
        for (int ks = 0; ks < 4; ++ks) {
            uu a0, a1, a2, a3, l0, l1, l2, l3;
            ldm4(aoffA + xb0 + ks * 32,         a0, a1, a2, a3);
            ldm4(aoffA + xb0 + XLOFF + ks * 32, l0, l1, l2, l3);
            uu bh00, bh01, bh10, bh11, bl00, bl01, bl10, bl11;
            ldm2(boffA + vb0 + ks * 32,                        bh00, bh01);
            ldm2(boffA + vb0 + 8 * XROW + ks * 32,             bh10, bh11);
            ldm2(boffA + vb0 + VLOFF + ks * 32,                bl00, bl01);
            ldm2(boffA + vb0 + VLOFF + 8 * XROW + ks * 32,     bl10, bl11);
            mma16816(acc[0], a0, a1, a2, a3, bh00, bh01);
            mma16816(acc[0], a0, a1, a2, a3, bl00, bl01);
            mma16816(acc[0], l0, l1, l2, l3, bh00, bh01);
            mma16816(acc[1], a0, a1, a2, a3, bh10, bh11);
            mma16816(acc[1], a0, a1, a2, a3, bl10, bl11);
            mma16816(acc[1], l0, l1, l2, l3, bh10, bh11);
        }
        __syncthreads();
    }

    // Stage-B first prefetch (chunk 15 — reverse order) overlaps logits/softmax.
    loadX(15, 0); CPA_COMMIT();

    // write logits to lsh[s][nc]
    {
        const int m  = lane >> 2;
        const int n2 = (lane & 3) * 2;
        const int sr = w * 16 + m;
        #pragma unroll
        for (int n8 = 0; n8 < 2; ++n8) {
            lsh[sr * 16 + n8 * 8 + n2]           = acc[n8][0];
            lsh[sr * 16 + n8 * 8 + n2 + 1]       = acc[n8][1];
            lsh[(sr + 8) * 16 + n8 * 8 + n2]     = acc[n8][2];
            lsh[(sr + 8) * 16 + n8 * 8 + n2 + 1] = acc[n8][3];
        }
    }
    __syncthreads();

    // softmax, write c^T[nc][s] as bf16 hi/lo
    if (t < SCHUNK) {
        float l[NCAP];
        #pragma unroll
        for (int i = 0; i < NCAP; ++i) l[i] = lsh[t * NCAP + i];
        float m = l[0];
        #pragma unroll
        for (int i = 1; i < NCAP; ++i) m = fmaxf(m, l[i]);
        float e[NCAP]; float ssum = 0.f;
        #pragma unroll
        for (int i = 0; i < NCAP; ++i) { e[i] = __expf(l[i] - m); ssum += e[i]; }
        float inv = 1.0f / ssum;
        #pragma unroll
        for (int i = 0; i < NCAP; ++i) {
            float c = e[i] * inv;
            __nv_bfloat16 ch = __float2bfloat16_rn(c);
            smCh[i * 136 + t] = ch;
            smCl[i * 136 + t] = __float2bfloat16_rn(c - __bfloat162float(ch));
        }
    }

    // ============================ Stage B (reverse chunk order) ============
    const int mt  = w & 3;
    const int nt8 = w >> 2;
    const uu aoffB = smb + (uu)(((lane & 7) + (lane >> 4) * 8) * XROW + (mt * 16 + ((lane >> 3) & 1) * 8) * 2);
    const uu coffH = su(smCh) + (uu)(nt8 * 8 * CROW + (lane & 7) * CROW + ((lane >> 3) & 1) * 16);
    const uu coffL = su(smCl) + (uu)(nt8 * 8 * CROW + (lane & 7) * CROW + ((lane >> 3) & 1) * 16);
    float* Yb = g_Y + ((size_t)b * NCAP * NHID) * NSPLIT + split;

    for (int i = 0; i < 16; ++i) {
        const int kc = 15 - i;
        if (i < 15) {
            loadX(kc - 1, (i + 1) & 1);
            CPA_COMMIT();
            CPA_WAIT1();
        } else {
            CPA_WAIT0();
        }
        __syncthreads();
        const uu xb0 = (uu)((i & 1) * XBUF);

        float y[4];
        y[0] = 0.f; y[1] = 0.f; y[2] = 0.f; y[3] = 0.f;

        #pragma unroll
        for (int ks = 0; ks < 8; ++ks) {
            uu a0, a1, a2, a3, l0, l1, l2, l3;
            ldm4t(aoffB + xb0 + ks * 16 * XROW,         a0, a1, a2, a3);
            ldm4t(aoffB + xb0 + XLOFF + ks * 16 * XROW, l0, l1, l2, l3);
            uu c0, c1, d0, d1;
            ldm2(coffH + ks * 32, c0, c1);
            ldm2(coffL + ks * 32, d0, d1);
            mma16816(y, a0, a1, a2, a3, c0, c1);
            mma16816(y, a0, a1, a2, a3, d0, d1);
            mma16816(y, l0, l1, l2, l3, c0, c1);
        }
        __syncthreads();

        const int m  = lane >> 2;
        const int n2 = (lane & 3) * 2;
        const int hg = kc * 64 + mt * 16 + m;
        const int nc = nt8 * 8 + n2;
        Yb[(size_t)(nc * NHID + hg) * 4]           = y[0];
        Yb[(size_t)((nc + 1) * NHID + hg) * 4]     = y[1];
        Yb[(size_t)(nc * NHID + hg + 8) * 4]       = y[2];
        Yb[(size_t)((nc + 1) * NHID + hg + 8) * 4] = y[3];
    }
}

// U1: opart[p][b][nc][dc] = sum_{hh in 64-part} (sum_splits Y) * W
__global__ void __launch_bounds__(256)
u1_kernel(const float* __restrict__ W, int iter) {
    __shared__ float Wsh[64 * 64];
    __shared__ float ysh[64 * 65];

    const int nc = blockIdx.x;
    const int p  = blockIdx.y;
    const int h0 = p * 64;
    const int t  = threadIdx.x;
    const int ncY = (iter == 0) ? 0 : nc;

    #pragma unroll
    for (int k = 0; k < 16; ++k) {
        int idx = t + k * 256;
        int hh = idx >> 6, dc = idx & 63;
        Wsh[hh * 64 + dc] = W[(size_t)(h0 + hh) * (NCAP * NDIM) + nc * NDIM + dc];
    }
    #pragma unroll
    for (int k = 0; k < 16; ++k) {
        int idx = t + k * 256;
        int b = idx >> 6, hh = idx & 63;
        float4 v = reinterpret_cast<const float4*>(g_Y)[
            (size_t)(b * NCAP + ncY) * NHID + h0 + hh];
        ysh[b * 65 + hh] = (v.x + v.y) + (v.z + v.w);
    }
    __syncthreads();

    const int dc4  = (t & 15) * 4;
    const int brow = (t >> 4) * 4;
    float4 a0 = make_float4(0,0,0,0), a1 = a0, a2 = a0, a3 = a0;
    #pragma unroll 4
    for (int hh = 0; hh < 64; ++hh) {
        float4 w4 = *reinterpret_cast<const float4*>(&Wsh[hh * 64 + dc4]);
        fma4(a0, w4, ysh[(brow + 0) * 65 + hh]);
        fma4(a1, w4, ysh[(brow + 1) * 65 + hh]);
        fma4(a2, w4, ysh[(brow + 2) * 65 + hh]);
        fma4(a3, w4, ysh[(brow + 3) * 65 + hh]);
    }
    #pragma unroll
    for (int i = 0; i < 4; ++i) {
        float4 a = (i == 0) ? a0 : (i == 1) ? a1 : (i == 2) ? a2 : a3;
        *reinterpret_cast<float4*>(g_opart + (((size_t)p * NBATCH + brow + i) * NCAP + nc) * NDIM + dc4) = a;
    }
}

// squash (iter 3 only): sum 16 partials, normalize, write output.
__global__ void __launch_bounds__(256)
squash_kernel(float* __restrict__ Og) {
    const int b = blockIdx.x;
    const int t = threadIdx.x;
    const int nc = t >> 4;
    const int q  = t & 15;

    float4 a = make_float4(0,0,0,0);
    #pragma unroll
    for (int p = 0; p < NPART; ++p) {
        float4 v = *(reinterpret_cast<const float4*>(
            g_opart + (((size_t)p * NBATCH + b) * NCAP + nc) * NDIM) + q);
        a.x += v.x; a.y += v.y; a.z += v.z; a.w += v.w;
    }
    float ss = a.x * a.x + a.y * a.y + a.z * a.z + a.w * a.w;
    #pragma unroll
    for (int off = 8; off > 0; off >>= 1) ss += __shfl_xor_sync(0xffffffffu, ss, off);
    float inv = rsqrtf(ss + 1e-7f);
    a.x *= inv; a.y *= inv; a.z *= inv; a.w *= inv;

    *(reinterpret_cast<float4*>(Og + ((size_t)b * NCAP + nc) * NDIM) + q) = a;
}

// U2S (fused squash + u2, iters 0-2): CTA = (nc, h-part p).
__global__ void __launch_bounds__(256)
u2s_kernel(const float* __restrict__ W, int iter) {
    __shared__ float WshT[64 * 68];
    __shared__ float osh[64 * 64];

    const int nc = blockIdx.x;
    const int p  = blockIdx.y;
    const int h0 = p * 64;
    const int t  = threadIdx.x;

    // ---- Phase 0: load+sum opart, squash ----
    {
        const int b  = t >> 2;
        const int dq = (t & 3) * 4;
        float4 r0 = make_float4(0,0,0,0), r1 = r0, r2 = r0, r3 = r0;
        #pragma unroll
        for (int pp = 0; pp < NPART; ++pp) {
            const float4* src = reinterpret_cast<const float4*>(
                g_opart + (((size_t)pp * NBATCH + b) * NCAP + nc) * NDIM) + dq;
            float4 v0 = src[0], v1 = src[1], v2 = src[2], v3 = src[3];
            r0.x += v0.x; r0.y += v0.y; r0.z += v0.z; r0.w += v0.w;
            r1.x += v1.x; r1.y += v1.y; r1.z += v1.z; r1.w += v1.w;
            r2.x += v2.x; r2.y += v2.y; r2.z += v2.z; r2.w += v2.w;
            r3.x += v3.x; r3.y += v3.y; r3.z += v3.z; r3.w += v3.w;
        }
        float ss = r0.x*r0.x + r0.y*r0.y + r0.z*r0.z + r0.w*r0.w
                 + r1.x*r1.x + r1.y*r1.y + r1.z*r1.z + r1.w*r1.w
                 + r2.x*r2.x + r2.y*r2.y + r2.z*r2.z + r2.w*r2.w
                 + r3.x*r3.x + r3.y*r3.y + r3.z*r3.z + r3.w*r3.w;
        ss += __shfl_xor_sync(0xffffffffu, ss, 1);
        ss += __shfl_xor_sync(0xffffffffu, ss, 2);
        float inv = rsqrtf(ss + 1e-7f);
        float4* orow = reinterpret_cast<float4*>(&osh[b * 64]) + dq;
        r0.x *= inv; r0.y *= inv; r0.z *= inv; r0.w *= inv;
        r1.x *= inv; r1.y *= inv; r1.z *= inv; r1.w *= inv;
        r2.x *= inv; r2.y *= inv; r2.z *= inv; r2.w *= inv;
        r3.x *= inv; r3.y *= inv; r3.z *= inv; r3.w *= inv;
        orow[0] = r0; orow[1] = r1; orow[2] = r2; orow[3] = r3;
    }

    #pragma unroll
    for (int k = 0; k < 16; ++k) {
        int idx = t + k * 256;
        int hh = idx >> 6, dc = idx & 63;
        WshT[dc * 68 + hh] = W[(size_t)(h0 + hh) * (NCAP * NDIM) + nc * NDIM + dc];
    }
    __syncthreads();

    // ---- Phase 1: rank update ----
    const int hh4  = (t & 15) * 4;
    const int brow = (t >> 4) * 4;
    float4 a0 = make_float4(0,0,0,0), a1 = a0, a2 = a0, a3 = a0;
    #pragma unroll 4
    for (int dc = 0; dc < 64; ++dc) {
        float4 w4 = *reinterpret_cast<const float4*>(&WshT[dc * 68 + hh4]);
        fma4(a0, w4, osh[(brow + 0) * 64 + dc]);
        fma4(a1, w4, osh[(brow + 1) * 64 + dc]);
        fma4(a2, w4, osh[(brow + 2) * 64 + dc]);
        fma4(a3, w4, osh[(brow + 3) * 64 + dc]);
    }
    #pragma unroll
    for (int i = 0; i < 4; ++i) {
        float4 a = (i == 0) ? a0 : (i == 1) ? a1 : (i == 2) ? a2 : a3;
        const size_t base = (((size_t)(brow + i)) * NCAP + nc) * NHID + h0 + hh4;
        float4* vp = reinterpret_cast<float4*>(g_V + base);
        float4 v;
        if (iter == 0) {
            v = a;
        } else {
            v = *vp;
            v.x += a.x; v.y += a.y; v.z += a.z; v.w += a.w;
        }
        *vp = v;
        uint2 uh, ul;
        cvt_hilo(v, uh, ul);
        *reinterpret_cast<uint2*>(g_Vh + base) = uh;
        *reinterpret_cast<uint2*>(g_Vl + base) = ul;
    }
}

extern "C" void kernel_launch(void* const* d_in, const int* in_sizes, int n_in,
                              void* d_out, int out_size) {
    (void)n_in; (void)out_size;
    const float* X = (const float*)d_in[0];
    const float* W = (const float*)d_in[1];
    if (in_sizes[0] == NHID * NCAP * NDIM) { const float* tmp = X; X = W; W = tmp; }

    cudaFuncSetAttribute(pass_kernel, cudaFuncAttributeMaxDynamicSharedMemorySize, SM_TOTAL);

    float* out = (float*)d_out;
    for (int iter = 0; iter < 4; ++iter) {
        pass_kernel<<<dim3(NSPLIT, NBATCH), 256, SM_TOTAL>>>(X, iter);
        u1_kernel<<<dim3(NCAP, NPART), 256>>>(W, iter);
        if (iter < 3) {
            u2s_kernel<<<dim3(NCAP, NPART), 256>>>(W, iter);
        } else {
            squash_kernel<<<NBATCH, 256>>>(out);
        }
    }
}